// round 2
// baseline (speedup 1.0000x reference)
#include <cuda_runtime.h>
#include <cuda_fp16.h>
#include <cuda_bf16.h>
#include <cstdint>
#include <cstddef>

// Sizes: hidden (2,4096,2048) f32; Win (6144,2048); conv_w (2048,1,3); Wout (2048,2048)
// M = 8192, K = 2048, N1 = 6144, N2 = 2048.

#define MDIM 8192
#define KDIM 2048
#define N1   6144
#define SEQMASK 4095

// ---------------- device scratch (no allocation APIs allowed) ----------------
__device__ __half g_A [MDIM * KDIM];      // 32 MB fp16 hidden
__device__ __half g_W1[N1   * KDIM];      // 24 MB fp16 Win
__device__ __half g_W2[KDIM * KDIM];      // 8 MB  fp16 Wout
__device__ __half g_y [MDIM * KDIM];      // 32 MB fp16 conv output
__device__ float  g_BCx[(size_t)MDIM * N1]; // 192 MB fp32 GEMM1 output

// ---------------- helpers ----------------
__device__ __forceinline__ uint32_t smem_u32(const void* p) {
    uint32_t a;
    asm("{ .reg .u64 t; cvta.to.shared.u64 t, %1; cvt.u32.u64 %0, t; }" : "=r"(a) : "l"(p));
    return a;
}

__device__ __forceinline__ void cp16(uint32_t dst, const void* src) {
    asm volatile("cp.async.cg.shared.global [%0], [%1], 16;" :: "r"(dst), "l"(src));
}

__device__ __forceinline__ void ldsm_x4(uint32_t& r0, uint32_t& r1, uint32_t& r2, uint32_t& r3, uint32_t addr) {
    asm volatile("ldmatrix.sync.aligned.m8n8.x4.shared.b16 {%0,%1,%2,%3}, [%4];"
                 : "=r"(r0), "=r"(r1), "=r"(r2), "=r"(r3) : "r"(addr));
}

__device__ __forceinline__ void ldsm_x2(uint32_t& r0, uint32_t& r1, uint32_t addr) {
    asm volatile("ldmatrix.sync.aligned.m8n8.x2.shared.b16 {%0,%1}, [%2];"
                 : "=r"(r0), "=r"(r1) : "r"(addr));
}

__device__ __forceinline__ void mma16816(float* d, const uint32_t* a, const uint32_t* b) {
    asm volatile(
        "mma.sync.aligned.m16n8k16.row.col.f32.f16.f16.f32 "
        "{%0,%1,%2,%3}, {%4,%5,%6,%7}, {%8,%9}, {%0,%1,%2,%3};"
        : "+f"(d[0]), "+f"(d[1]), "+f"(d[2]), "+f"(d[3])
        : "r"(a[0]), "r"(a[1]), "r"(a[2]), "r"(a[3]), "r"(b[0]), "r"(b[1]));
}

// SW128 swizzle on a byte offset within a 1024B-aligned tile
#define SWZ(o) ((o) ^ (((o) >> 3) & 0x70))

// ---------------- f32 -> f16 convert (4 elems / thread, exact grid) ----------------
__global__ void __launch_bounds__(256) convert_kernel(const float4* __restrict__ src,
                                                      uint2* __restrict__ dst) {
    int i = blockIdx.x * 256 + threadIdx.x;
    float4 v = src[i];
    __half2 a = __floats2half2_rn(v.x, v.y);
    __half2 b = __floats2half2_rn(v.z, v.w);
    uint2 u;
    u.x = *reinterpret_cast<unsigned*>(&a);
    u.y = *reinterpret_cast<unsigned*>(&b);
    dst[i] = u;
}

// ---------------- TN fp16 GEMM: C[M,N] = A[M,K] * W[N,K]^T, fp32 out ----------------
// BM=128, BN=128, BK=64 halfs (128B rows, SW128), 3 stages, 256 threads (8 warps 2x4),
// warp tile 64(m) x 32(n) = 4x4 m16n8k16 frags.
__global__ void __launch_bounds__(256, 1) hgemm_tn(const __half* __restrict__ A,
                                                   const __half* __restrict__ W,
                                                   float* __restrict__ C, int ldc) {
    constexpr int K = KDIM;          // 2048
    constexpr int KT = K / 64;       // 32 k-tiles
    extern __shared__ char smem[];
    const int t = threadIdx.x;
    const int tm = blockIdx.y * 128;
    const int tn = blockIdx.x * 128;

    const uint32_t sbase = smem_u32(smem);
    const uint32_t saA = sbase;                 // 3 * 16384
    const uint32_t saB = sbase + 3 * 16384;     // 3 * 16384

    auto load_stage = [&](int st, int kt) {
        const __half* Ag = A + (size_t)tm * K + kt * 64;
        const __half* Wg = W + (size_t)tn * K + kt * 64;
        #pragma unroll
        for (int p = 0; p < 4; p++) {
            int id = p * 256 + t;
            int r = id >> 3, c = id & 7;           // row 0..127, 16B chunk 0..7
            cp16(saA + st * 16384 + SWZ(r * 128 + c * 16), Ag + (size_t)r * K + c * 8);
            cp16(saB + st * 16384 + SWZ(r * 128 + c * 16), Wg + (size_t)r * K + c * 8);
        }
    };

    float acc[16][4] = {};

    load_stage(0, 0);
    asm volatile("cp.async.commit_group;" ::: "memory");
    load_stage(1, 1);
    asm volatile("cp.async.commit_group;" ::: "memory");

    const int warp = t >> 5, lane = t & 31;
    const int wm = (warp >> 2) * 64;   // 2 warps in m
    const int wn = (warp & 3) * 32;    // 4 warps in n
    // ldmatrix lane->row mapping
    const int g = lane >> 3;
    const int a_row = (g & 1) * 8 + (lane & 7);   // 0..15 within 16-row tile
    const int a_kb  = (g >> 1) * 16;              // byte offset 0 or 16 (k 0-7 / 8-15)
    const int lg = lane & 15;
    const int b_row = lg & 7;
    const int b_kb  = (lg >> 3) * 16;

    for (int kt = 0; kt < KT; kt++) {
        asm volatile("cp.async.wait_group 1;" ::: "memory");
        __syncthreads();
        if (kt + 2 < KT) load_stage((kt + 2) % 3, kt + 2);
        asm volatile("cp.async.commit_group;" ::: "memory");

        const int st = kt % 3;
        const uint32_t aT = saA + st * 16384;
        const uint32_t bT = saB + st * 16384;
        #pragma unroll
        for (int ks = 0; ks < 4; ks++) {          // 4 k16 steps per 64-k tile
            uint32_t a[4][4], b[4][2];
            #pragma unroll
            for (int mt = 0; mt < 4; mt++)
                ldsm_x4(a[mt][0], a[mt][1], a[mt][2], a[mt][3],
                        aT + SWZ((wm + mt * 16 + a_row) * 128 + ks * 32 + a_kb));
            #pragma unroll
            for (int nt = 0; nt < 4; nt++)
                ldsm_x2(b[nt][0], b[nt][1],
                        bT + SWZ((wn + nt * 8 + b_row) * 128 + ks * 32 + b_kb));
            #pragma unroll
            for (int mt = 0; mt < 4; mt++)
                #pragma unroll
                for (int nt = 0; nt < 4; nt++)
                    mma16816(acc[mt * 4 + nt], a[mt], b[nt]);
        }
    }

    // epilogue: fp32 to C
    #pragma unroll
    for (int mt = 0; mt < 4; mt++) {
        #pragma unroll
        for (int nt = 0; nt < 4; nt++) {
            const float* d = acc[mt * 4 + nt];
            int row = tm + wm + mt * 16 + (lane >> 2);
            int col = tn + wn + nt * 8 + (lane & 3) * 2;
            *reinterpret_cast<float2*>(C + (size_t)row * ldc + col)       = make_float2(d[0], d[1]);
            *reinterpret_cast<float2*>(C + (size_t)(row + 8) * ldc + col) = make_float2(d[2], d[3]);
        }
    }
}

// ---------------- fused B*x -> causal depthwise conv(L=3) -> *C, fp16 out ----------------
__global__ void __launch_bounds__(256) shortconv_kernel(const float* __restrict__ BCx,
                                                        const float* __restrict__ cw,
                                                        __half* __restrict__ y) {
    int gid = blockIdx.x * 256 + threadIdx.x;  // 8192 * 512
    int m = gid >> 9;
    int h = (gid & 511) * 4;
    int s = m & SEQMASK;

    const float* row0 = BCx + (size_t)m * N1;
    float4 B0 = *reinterpret_cast<const float4*>(row0 + h);
    float4 Cc = *reinterpret_cast<const float4*>(row0 + 2048 + h);
    float4 X0 = *reinterpret_cast<const float4*>(row0 + 4096 + h);
    float4 B1 = make_float4(0.f, 0.f, 0.f, 0.f), X1 = B1, B2 = B1, X2 = B1;
    if (s >= 1) {
        const float* r1 = row0 - N1;
        B1 = *reinterpret_cast<const float4*>(r1 + h);
        X1 = *reinterpret_cast<const float4*>(r1 + 4096 + h);
    }
    if (s >= 2) {
        const float* r2 = row0 - 2 * N1;
        B2 = *reinterpret_cast<const float4*>(r2 + h);
        X2 = *reinterpret_cast<const float4*>(r2 + 4096 + h);
    }

    const float* b0 = reinterpret_cast<const float*>(&B0);
    const float* b1 = reinterpret_cast<const float*>(&B1);
    const float* b2 = reinterpret_cast<const float*>(&B2);
    const float* x0 = reinterpret_cast<const float*>(&X0);
    const float* x1 = reinterpret_cast<const float*>(&X1);
    const float* x2 = reinterpret_cast<const float*>(&X2);
    const float* cc = reinterpret_cast<const float*>(&Cc);

    float out[4];
    #pragma unroll
    for (int j = 0; j < 4; j++) {
        float w0 = cw[(h + j) * 3 + 0];
        float w1 = cw[(h + j) * 3 + 1];
        float w2 = cw[(h + j) * 3 + 2];
        // out[s] = C[s] * (w0*Bx[s-2] + w1*Bx[s-1] + w2*Bx[s])
        out[j] = cc[j] * (w0 * b2[j] * x2[j] + w1 * b1[j] * x1[j] + w2 * b0[j] * x0[j]);
    }
    __half2 h0 = __floats2half2_rn(out[0], out[1]);
    __half2 h1 = __floats2half2_rn(out[2], out[3]);
    *reinterpret_cast<__half2*>(y + (size_t)m * KDIM + h)     = h0;
    *reinterpret_cast<__half2*>(y + (size_t)m * KDIM + h + 2) = h1;
}

// ---------------- launch ----------------
extern "C" void kernel_launch(void* const* d_in, const int* in_sizes, int n_in,
                              void* d_out, int out_size) {
    const float* hs   = (const float*)d_in[0];   // (2,4096,2048)
    const float* Win  = (const float*)d_in[1];   // (6144,2048)
    const float* cw   = (const float*)d_in[2];   // (2048,1,3)
    const float* Wout = (const float*)d_in[3];   // (2048,2048)
    float* out = (float*)d_out;

    void *pA, *pW1, *pW2, *pY, *pBCx;
    cudaGetSymbolAddress(&pA,  g_A);
    cudaGetSymbolAddress(&pW1, g_W1);
    cudaGetSymbolAddress(&pW2, g_W2);
    cudaGetSymbolAddress(&pY,  g_y);
    cudaGetSymbolAddress(&pBCx, g_BCx);

    cudaFuncSetAttribute(hgemm_tn, cudaFuncAttributeMaxDynamicSharedMemorySize, 98304);

    // f32 -> f16 converts (element counts all divisible by 1024)
    convert_kernel<<<16384, 256>>>((const float4*)hs,   (uint2*)pA);   // 16.7M elems
    convert_kernel<<<12288, 256>>>((const float4*)Win,  (uint2*)pW1);  // 12.6M
    convert_kernel<<<4096,  256>>>((const float4*)Wout, (uint2*)pW2);  // 4.2M

    // GEMM1: BCx[8192,6144] = A * Win^T
    hgemm_tn<<<dim3(N1 / 128, MDIM / 128), 256, 98304>>>(
        (const __half*)pA, (const __half*)pW1, (float*)pBCx, N1);

    // fused Bx, causal conv, *C  -> y fp16
    shortconv_kernel<<<(MDIM * KDIM / 4) / 256, 256>>>((const float*)pBCx, cw, (__half*)pY);

    // GEMM2: out[8192,2048] = y * Wout^T
    hgemm_tn<<<dim3(KDIM / 128, MDIM / 128), 256, 98304>>>(
        (const __half*)pY, (const __half*)pW2, out, KDIM);
}